// round 2
// baseline (speedup 1.0000x reference)
#include <cuda_runtime.h>
#include <cuda_bf16.h>

// Problem constants
#define Bn   4
#define Tn   1024
#define Dn   512
#define Hn   8
#define Ln   6
#define Vn   128
#define DFFn 2048
#define BT   (Bn*Tn)          // 4096 token rows

// ---------------------------------------------------------------------------
// Scratch (device globals; allocation is forbidden)
// ---------------------------------------------------------------------------
__device__ float g_x  [BT*Dn];             // residual stream          8 MB
__device__ float g_q  [Hn*BT*Dn];          // [H,B,T,D]               64 MB
__device__ float g_k  [Hn*BT*Dn];          //                         64 MB
__device__ float g_v  [Hn*BT*Dn];          //                         64 MB
__device__ float g_att[(long)Hn*Bn*Tn*Tn]; // [H*B,T,T]              128 MB
__device__ float g_oc [BT*Hn*Dn];          // concat heads [BT,H*D]   64 MB
__device__ float g_tmp[BT*Dn];             //                          8 MB
__device__ float g_h1 [BT*DFFn];           // MLP hidden              32 MB
__device__ float g_xf [BT*Dn];             //                          8 MB
__device__ float g_rowloss[BT];

// ---------------------------------------------------------------------------
// Batched SGEMM, 128x128 tile, 16-deep K panel, 8x8 per-thread microtile
// (2x2 blocks of 4x4 at stride 64 -> all shared traffic is float4).
//   A: row-major [M,K], per-batch offset z*aStride
//   B: row-major [K,N] (TRANSB=0) or [N,K] (TRANSB=1), offset z*bStride
//   C: row stride ldc, per-batch offset (z/cdiv)*cs1 + (z%cdiv)*cs2
//   Every call site has M%128==0, N%128==0, K%16==0.
// ---------------------------------------------------------------------------
#define BMt 128
#define BNt 128
#define BKt 16

template<bool TRANSB>
__global__ __launch_bounds__(256)
void gemm_k(const float* __restrict__ A, const float* __restrict__ Bm,
            const float* __restrict__ bias, float* __restrict__ C,
            int M, int N, int K,
            long aStride, long bStride, long biasStride,
            int cdiv, long cs1, long cs2, int ldc, int relu)
{
    __shared__ float As[BKt][BMt + 4];
    __shared__ float Bs[BKt][BNt + 4];

    const int z = blockIdx.z;
    const float* Ab = A  + (long)z * aStride;
    const float* Bb = Bm + (long)z * bStride;
    float*       Cb = C  + (long)(z / cdiv) * cs1 + (long)(z % cdiv) * cs2;
    const float* biasb = bias ? (bias + (long)z * biasStride) : nullptr;

    const int m0 = blockIdx.y * BMt;
    const int n0 = blockIdx.x * BNt;
    const int tid = threadIdx.x;
    const int tx = tid & 15;    // 0..15  (N direction)
    const int ty = tid >> 4;    // 0..15  (M direction)

    float acc[8][8] = {};

    // A-tile loader indices: 2 float4 per thread (rows r and r+64)
    const int arow  = tid >> 2;         // 0..63
    const int acol4 = (tid & 3) * 4;    // 0,4,8,12

    for (int k0 = 0; k0 < K; k0 += BKt) {
        // ---- A tile 128x16, stored transposed As[k][m] ----
        #pragma unroll
        for (int h = 0; h < 2; h++) {
            const int r = arow + h * 64;
            float4 av = *(const float4*)(Ab + (long)(m0 + r) * K + k0 + acol4);
            As[acol4 + 0][r] = av.x;
            As[acol4 + 1][r] = av.y;
            As[acol4 + 2][r] = av.z;
            As[acol4 + 3][r] = av.w;
        }
        // ---- B tile -> Bs[k][n] ----
        if (!TRANSB) {
            const int brow  = tid >> 5;         // 0..7 (+8)
            const int bcol4 = (tid & 31) * 4;   // 0..124
            #pragma unroll
            for (int h = 0; h < 2; h++) {
                const int r = brow + h * 8;
                float4 bv = *(const float4*)(Bb + (long)(k0 + r) * N + n0 + bcol4);
                *(float4*)&Bs[r][bcol4] = bv;
            }
        } else {
            const int bn  = tid >> 2;           // 0..63 (+64)
            const int bk4 = (tid & 3) * 4;      // 0,4,8,12
            #pragma unroll
            for (int h = 0; h < 2; h++) {
                const int r = bn + h * 64;
                float4 bv = *(const float4*)(Bb + (long)(n0 + r) * K + k0 + bk4);
                Bs[bk4 + 0][r] = bv.x;
                Bs[bk4 + 1][r] = bv.y;
                Bs[bk4 + 2][r] = bv.z;
                Bs[bk4 + 3][r] = bv.w;
            }
        }
        __syncthreads();

        #pragma unroll
        for (int kk = 0; kk < BKt; kk++) {
            float ra[8], rb[8];
            *(float4*)&ra[0] = *(const float4*)&As[kk][ty * 4];
            *(float4*)&ra[4] = *(const float4*)&As[kk][ty * 4 + 64];
            *(float4*)&rb[0] = *(const float4*)&Bs[kk][tx * 4];
            *(float4*)&rb[4] = *(const float4*)&Bs[kk][tx * 4 + 64];
            #pragma unroll
            for (int i = 0; i < 8; i++)
                #pragma unroll
                for (int j = 0; j < 8; j++)
                    acc[i][j] += ra[i] * rb[j];
        }
        __syncthreads();
    }

    // Epilogue: 2x2 blocks of 4x4
    #pragma unroll
    for (int ib = 0; ib < 2; ib++) {
        #pragma unroll
        for (int i = 0; i < 4; i++) {
            const int m = m0 + ib * 64 + ty * 4 + i;
            #pragma unroll
            for (int jb = 0; jb < 2; jb++) {
                const int n = n0 + jb * 64 + tx * 4;
                float* crow = Cb + (long)m * ldc + n;
                #pragma unroll
                for (int j = 0; j < 4; j++) {
                    float v0 = acc[ib * 4 + i][jb * 4 + j];
                    if (biasb) v0 += biasb[n + j];
                    if (relu)  v0 = fmaxf(v0, 0.f);
                    crow[j] = v0;
                }
            }
        }
    }
}

// ---------------------------------------------------------------------------
// Embedding lookup
// ---------------------------------------------------------------------------
__global__ void embed_k(const int* __restrict__ tokens,
                        const float* __restrict__ emb, float* __restrict__ x)
{
    int i = blockIdx.x * blockDim.x + threadIdx.x;
    if (i < BT * Dn)
        x[i] = emb[(long)tokens[i / Dn] * Dn + (i % Dn)];
}

// ---------------------------------------------------------------------------
// Causal softmax (no 1/sqrt(d) scale — faithful to reference).
// One block per (z, row t); 256 threads, 4 elems each (T=1024).
// ---------------------------------------------------------------------------
__global__ __launch_bounds__(256)
void softmax_causal_k(float* __restrict__ att)
{
    const int t = blockIdx.x;
    const long z = blockIdx.y;
    float* row = att + z * (long)Tn * Tn + (long)t * Tn;
    const int tid = threadIdx.x;

    __shared__ float red[256];
    float r[4];
    float mx = -1e30f;
    #pragma unroll
    for (int i = 0; i < 4; i++) {
        int s = tid + i * 256;
        r[i] = (s <= t) ? row[s] : -1e30f;
        mx = fmaxf(mx, r[i]);
    }
    red[tid] = mx; __syncthreads();
    for (int off = 128; off > 0; off >>= 1) {
        if (tid < off) red[tid] = fmaxf(red[tid], red[tid + off]);
        __syncthreads();
    }
    mx = red[0]; __syncthreads();

    float sum = 0.f;
    #pragma unroll
    for (int i = 0; i < 4; i++) {
        int s = tid + i * 256;
        r[i] = (s <= t) ? __expf(r[i] - mx) : 0.f;
        sum += r[i];
    }
    red[tid] = sum; __syncthreads();
    for (int off = 128; off > 0; off >>= 1) {
        if (tid < off) red[tid] += red[tid + off];
        __syncthreads();
    }
    const float inv = 1.f / red[0];
    #pragma unroll
    for (int i = 0; i < 4; i++)
        row[tid + i * 256] = r[i] * inv;
}

// ---------------------------------------------------------------------------
// y = LayerNorm(xin + delta) * g + b   (delta may be null). One block / row.
// ---------------------------------------------------------------------------
__global__ __launch_bounds__(256)
void add_ln_k(const float* __restrict__ xin, const float* __restrict__ delta,
              float* __restrict__ xout,
              const float* __restrict__ g, const float* __restrict__ b)
{
    const int row = blockIdx.x;
    const int tid = threadIdx.x;
    const long base = (long)row * Dn;

    float v0 = xin[base + tid]       + (delta ? delta[base + tid]       : 0.f);
    float v1 = xin[base + tid + 256] + (delta ? delta[base + tid + 256] : 0.f);

    __shared__ float s1[256], s2[256];
    s1[tid] = v0 + v1;
    s2[tid] = v0 * v0 + v1 * v1;
    __syncthreads();
    for (int off = 128; off > 0; off >>= 1) {
        if (tid < off) { s1[tid] += s1[tid + off]; s2[tid] += s2[tid + off]; }
        __syncthreads();
    }
    const float mean = s1[0] * (1.f / Dn);
    const float var  = s2[0] * (1.f / Dn) - mean * mean;
    const float rstd = rsqrtf(var + 1e-5f);

    xout[base + tid]       = (v0 - mean) * rstd * g[tid]       + b[tid];
    xout[base + tid + 256] = (v1 - mean) * rstd * g[tid + 256] + b[tid + 256];
}

// ---------------------------------------------------------------------------
// Per-row cross-entropy: rowloss[row] = logsumexp(row) - logits[row][label]
// ---------------------------------------------------------------------------
__global__ __launch_bounds__(128)
void loss_rows_k(const float* __restrict__ logits, const int* __restrict__ labels,
                 float* __restrict__ rowloss)
{
    const int row = blockIdx.x;
    const int tid = threadIdx.x;
    const float v = logits[(long)row * Vn + tid];

    __shared__ float red[128];
    red[tid] = v; __syncthreads();
    for (int off = 64; off > 0; off >>= 1) {
        if (tid < off) red[tid] = fmaxf(red[tid], red[tid + off]);
        __syncthreads();
    }
    const float mx = red[0]; __syncthreads();
    red[tid] = expf(v - mx); __syncthreads();
    for (int off = 64; off > 0; off >>= 1) {
        if (tid < off) red[tid] += red[tid + off];
        __syncthreads();
    }
    const float lse = mx + logf(red[0]);
    if (tid == labels[row]) rowloss[row] = lse - v;
}

// Deterministic tree reduction of the 4096 per-row losses -> mean.
__global__ __launch_bounds__(1024)
void loss_reduce_k(const float* __restrict__ rowloss, float* __restrict__ out)
{
    const int tid = threadIdx.x;
    float s = rowloss[tid] + rowloss[tid + 1024] +
              rowloss[tid + 2048] + rowloss[tid + 3072];
    __shared__ float red[1024];
    red[tid] = s; __syncthreads();
    for (int off = 512; off > 0; off >>= 1) {
        if (tid < off) red[tid] += red[tid + off];
        __syncthreads();
    }
    if (tid == 0) out[0] = red[0] * (1.f / (float)BT);
}

// ---------------------------------------------------------------------------
// Host driver (graph-capturable: kernel launches only)
// ---------------------------------------------------------------------------
extern "C" void kernel_launch(void* const* d_in, const int* in_sizes, int n_in,
                              void* d_out, int out_size)
{
    const int*   tokens = (const int*)  d_in[0];
    const int*   labels = (const int*)  d_in[1];
    const float* emb    = (const float*)d_in[2];
    const float* Wq     = (const float*)d_in[3];
    const float* bq     = (const float*)d_in[4];
    const float* Wk     = (const float*)d_in[5];
    const float* bk     = (const float*)d_in[6];
    const float* Wv     = (const float*)d_in[7];
    const float* bv     = (const float*)d_in[8];
    const float* Wo     = (const float*)d_in[9];
    const float* bo     = (const float*)d_in[10];
    const float* ln1_g  = (const float*)d_in[11];
    const float* ln1_b  = (const float*)d_in[12];
    const float* W1     = (const float*)d_in[13];
    const float* b1     = (const float*)d_in[14];
    const float* W2     = (const float*)d_in[15];
    const float* b2     = (const float*)d_in[16];
    const float* ln2_g  = (const float*)d_in[17];
    const float* ln2_b  = (const float*)d_in[18];
    const float* lnf_g  = (const float*)d_in[19];
    const float* lnf_b  = (const float*)d_in[20];
    const float* Wout   = (const float*)d_in[21];
    const float* bout   = (const float*)d_in[22];
    float* out = (float*)d_out;

    float *x, *q, *k, *v, *att, *oc, *tmp, *h1, *xf, *rowloss;
    cudaGetSymbolAddress((void**)&x,   g_x);
    cudaGetSymbolAddress((void**)&q,   g_q);
    cudaGetSymbolAddress((void**)&k,   g_k);
    cudaGetSymbolAddress((void**)&v,   g_v);
    cudaGetSymbolAddress((void**)&att, g_att);
    cudaGetSymbolAddress((void**)&oc,  g_oc);
    cudaGetSymbolAddress((void**)&tmp, g_tmp);
    cudaGetSymbolAddress((void**)&h1,  g_h1);
    cudaGetSymbolAddress((void**)&xf,  g_xf);
    cudaGetSymbolAddress((void**)&rowloss, g_rowloss);

    // 1) embedding
    embed_k<<<(BT * Dn + 255) / 256, 256>>>(tokens, emb, x);

    const long HDD = (long)Hn * Dn * Dn;   // per-layer W{q,k,v} size
    for (int l = 0; l < Ln; l++) {
        // 2) QKV projections, batched over heads; q/k/v layout [H, B*T, D]
        dim3 gQKV(Dn / BNt, BT / BMt, Hn);
        gemm_k<false><<<gQKV, 256>>>(x, Wq + l * HDD, bq + (long)l * Hn * Dn, q,
                                     BT, Dn, Dn, 0, (long)Dn * Dn, Dn,
                                     1, (long)BT * Dn, 0, Dn, 0);
        gemm_k<false><<<gQKV, 256>>>(x, Wk + l * HDD, bk + (long)l * Hn * Dn, k,
                                     BT, Dn, Dn, 0, (long)Dn * Dn, Dn,
                                     1, (long)BT * Dn, 0, Dn, 0);
        gemm_k<false><<<gQKV, 256>>>(x, Wv + l * HDD, bv + (long)l * Hn * Dn, v,
                                     BT, Dn, Dn, 0, (long)Dn * Dn, Dn,
                                     1, (long)BT * Dn, 0, Dn, 0);

        // 3) scores = q @ k^T  (batch z = h*B + b over H*B)
        dim3 gS(Tn / BNt, Tn / BMt, Hn * Bn);
        gemm_k<true><<<gS, 256>>>(q, k, nullptr, att,
                                  Tn, Tn, Dn, (long)Tn * Dn, (long)Tn * Dn, 0,
                                  1, (long)Tn * Tn, 0, Tn, 0);

        // 4) causal softmax
        softmax_causal_k<<<dim3(Tn, Hn * Bn), 256>>>(att);

        // 5) o = attn @ v, written head-concatenated into oc[BT, H*D]
        //    z = h*B + b -> C offset h*D + b*(T*H*D), ldc = H*D
        dim3 gAV(Dn / BNt, Tn / BMt, Hn * Bn);
        gemm_k<false><<<gAV, 256>>>(att, v, nullptr, oc,
                                    Tn, Dn, Tn, (long)Tn * Tn, (long)Tn * Dn, 0,
                                    Bn, (long)Dn, (long)Tn * Hn * Dn, Hn * Dn, 0);

        // 6) output projection: tmp = oc @ Wo + bo
        dim3 gP(Dn / BNt, BT / BMt, 1);
        gemm_k<false><<<gP, 256>>>(oc, Wo + (long)l * Hn * Dn * Dn, bo + (long)l * Dn,
                                   tmp, BT, Dn, Hn * Dn, 0, 0, 0, 1, 0, 0, Dn, 0);

        // 7) x = LN(x + tmp; ln1)
        add_ln_k<<<BT, 256>>>(x, tmp, x, ln1_g + (long)l * Dn, ln1_b + (long)l * Dn);

        // 8) MLP (fused bias+ReLU in GEMM1)
        dim3 gF1(DFFn / BNt, BT / BMt, 1);
        gemm_k<false><<<gF1, 256>>>(x, W1 + (long)l * Dn * DFFn, b1 + (long)l * DFFn,
                                    h1, BT, DFFn, Dn, 0, 0, 0, 1, 0, 0, DFFn, 1);
        dim3 gF2(Dn / BNt, BT / BMt, 1);
        gemm_k<false><<<gF2, 256>>>(h1, W2 + (long)l * DFFn * Dn, b2 + (long)l * Dn,
                                    tmp, BT, Dn, DFFn, 0, 0, 0, 1, 0, 0, Dn, 0);

        // 9) x = LN(x + tmp; ln2)
        add_ln_k<<<BT, 256>>>(x, tmp, x, ln2_g + (long)l * Dn, ln2_b + (long)l * Dn);
    }

    // final LN
    add_ln_k<<<BT, 256>>>(x, nullptr, xf, lnf_g, lnf_b);

    // logits = xf @ Wout + bout  (directly into d_out)
    dim3 gL(Vn / BNt, BT / BMt, 1);
    gemm_k<false><<<gL, 256>>>(xf, Wout, bout, out,
                               BT, Vn, Dn, 0, 0, 0, 1, 0, 0, Vn, 0);

    // loss: deterministic two-stage reduce, appended after logits
    if (out_size > BT * Vn) {
        loss_rows_k<<<BT, 128>>>(out, labels, rowloss);
        loss_reduce_k<<<1, 1024>>>(rowloss, out + (long)BT * Vn);
    }
}